// round 1
// baseline (speedup 1.0000x reference)
#include <cuda_runtime.h>

#define NMOV 4096
#define NPHYS 4096
#define BLOCK 256
#define ITILES (NMOV / BLOCK)   // 16
#define JTILES (NMOV / BLOCK)   // 16
#define NBLOCKS (ITILES * JTILES)

__device__ float g_partials[NBLOCKS];

__global__ __launch_bounds__(BLOCK) void notch_main(
    const float* __restrict__ pos,
    const float* __restrict__ sx,
    const float* __restrict__ sy)
{
    __shared__ float4 tile[BLOCK];
    __shared__ float warpsum[BLOCK / 32];

    const int tid = threadIdx.x;
    const int i = blockIdx.x * BLOCK + tid;
    const int jbase = blockIdx.y * BLOCK;

    const float* __restrict__ x = pos;
    const float* __restrict__ y = pos + NPHYS;

    // Per-thread row constants
    const float xi  = x[i];
    const float yi  = y[i];
    const float hxi = 0.5f * sx[i];
    const float hyi = 0.5f * sy[i];

    // Cooperative load of the j-tile: {xj, yj, hxj, hyj}
    {
        const int j = jbase + tid;
        tile[tid] = make_float4(x[j], y[j], 0.5f * sx[j], 0.5f * sy[j]);
    }
    __syncthreads();

    float acc = 0.0f;
#pragma unroll 8
    for (int k = 0; k < BLOCK; ++k) {
        const float4 t = tile[k];
        float dx = fmaxf(fabsf(xi - t.x) - (hxi + t.z), 0.0f);
        float dy = fmaxf(fabsf(yi - t.y) - (hyi + t.w), 0.0f);
        float p  = fmaxf(2.0f - dx - dy, 0.0f);
        acc = fmaf(p, p, acc);
    }

    // Warp reduce
#pragma unroll
    for (int off = 16; off > 0; off >>= 1)
        acc += __shfl_xor_sync(0xFFFFFFFFu, acc, off);

    if ((tid & 31) == 0) warpsum[tid >> 5] = acc;
    __syncthreads();

    if (tid < 32) {
        float v = (tid < BLOCK / 32) ? warpsum[tid] : 0.0f;
#pragma unroll
        for (int off = 4; off > 0; off >>= 1)
            v += __shfl_xor_sync(0xFFFFFFFFu, v, off);
        if (tid == 0)
            g_partials[blockIdx.y * ITILES + blockIdx.x] = v;
    }
}

__global__ __launch_bounds__(NBLOCKS) void notch_reduce(float* __restrict__ out)
{
    __shared__ double warpsum[NBLOCKS / 32];
    const int tid = threadIdx.x;

    double v = (double)g_partials[tid];
#pragma unroll
    for (int off = 16; off > 0; off >>= 1)
        v += __shfl_xor_sync(0xFFFFFFFFu, v, off);

    if ((tid & 31) == 0) warpsum[tid >> 5] = v;
    __syncthreads();

    if (tid < 32) {
        double s = (tid < NBLOCKS / 32) ? warpsum[tid] : 0.0;
#pragma unroll
        for (int off = 4; off > 0; off >>= 1)
            s += __shfl_xor_sync(0xFFFFFFFFu, s, off);
        if (tid == 0) {
            // Full-matrix sum includes N diagonal terms of relu(2-0)^2 = 4 each.
            out[0] = (float)((s - 4.0 * (double)NMOV) * 0.5);
        }
    }
}

extern "C" void kernel_launch(void* const* d_in, const int* in_sizes, int n_in,
                              void* d_out, int out_size)
{
    (void)in_sizes; (void)n_in; (void)out_size;
    const float* pos = (const float*)d_in[0];
    // d_in[1] is macro_mask (bool) — unused by the reference computation.
    const float* sx  = (const float*)d_in[2];
    const float* sy  = (const float*)d_in[3];
    float* out = (float*)d_out;

    dim3 grid(ITILES, JTILES);
    notch_main<<<grid, BLOCK>>>(pos, sx, sy);
    notch_reduce<<<1, NBLOCKS>>>(out);
}